// round 7
// baseline (speedup 1.0000x reference)
#include <cuda_runtime.h>
#include <math.h>

#define H 1024
#define V 50257
#define S 4096
#define NT 256
#define NCHAIN 132            // chain blocks (co-resident, wave-1 by dispatch order)
#define WROWS 48              // rows per worker block (8 warps x 6 rows)
#define NWORK ((V + WROWS - 1) / WROWS)   // 1048 worker blocks

// ---------------- scratch (__device__ globals) ----------------
__device__ float g_gi[3 * H];
__device__ float g_gh[3 * H];
__device__ float g_h[H];
__device__ float g_vpart[32][H];
__device__ float g_v[H];
__device__ float g_scores[S];
__device__ float g_w[S];
__device__ float g_ctxpart[32][H];
__device__ float g_ctx[H];
__device__ unsigned g_cnt = 0;
__device__ unsigned g_gen = 0;
__device__ volatile unsigned g_hflag = 0;
__device__ volatile unsigned g_ctxflag = 0;

// ---------------- helpers ----------------
__device__ __forceinline__ float warp_sum(float v) {
#pragma unroll
    for (int o = 16; o; o >>= 1) v += __shfl_xor_sync(0xffffffffu, v, o);
    return v;
}

// partial grid barrier over the NCHAIN chain blocks only
__device__ __forceinline__ void chain_sync() {
    __syncthreads();
    if (threadIdx.x == 0) {
        __threadfence();
        unsigned gen = *(volatile unsigned*)&g_gen;
        if (atomicAdd(&g_cnt, 1u) == NCHAIN - 1) {
            g_cnt = 0;
            __threadfence();
            *(volatile unsigned*)&g_gen = gen + 1;
        } else {
            while (*(volatile unsigned*)&g_gen == gen) { }
        }
        __threadfence();
    }
    __syncthreads();
}

// warp dot: 1024 floats from ptr vs shared vec
__device__ __forceinline__ float warp_dot(const float4* __restrict__ p,
                                          const float4* vec, int lane) {
    float acc = 0.f;
#pragma unroll
    for (int it = 0; it < 8; it++) {
        float4 w = p[it * 32 + lane];
        float4 c = vec[it * 32 + lane];
        acc += w.x * c.x + w.y * c.y + w.z * c.z + w.w * c.w;
    }
    return warp_sum(acc);
}

// ---------------- reset flags each replay (runs before k_fused) ----------------
__global__ void k_reset() {
    g_hflag = 0;
    g_ctxflag = 0;
    __threadfence();
}

// ---------------- one fused launch: chain blocks + logits workers ----------------
__global__ void k_fused(const int* __restrict__ word,
                        const float* __restrict__ last_hidden,
                        const float* __restrict__ enc,
                        const float* __restrict__ emb,
                        const float* __restrict__ w_ih,
                        const float* __restrict__ w_hh,
                        const float* __restrict__ b_ih,
                        const float* __restrict__ b_hh,
                        const float* __restrict__ attn_w,
                        const float* __restrict__ out_w,
                        const float* __restrict__ out_b,
                        float* __restrict__ dout) {
    __shared__ float4 sbuf4[512];
    float* sbuf = (float*)sbuf4;

    const int t = threadIdx.x;
    const int b = blockIdx.x;
    const int warp = t >> 5, lane = t & 31;

    if (b >= NCHAIN) {
        // ================= logits worker =================
        const int w = b - NCHAIN;
        const int rbase = w * WROWS;

        // wait for h
        if (t == 0) while (g_hflag == 0) __nanosleep(64);
        __syncthreads();
        sbuf4[t] = reinterpret_cast<const float4*>(g_h)[t];   // h -> shared
        __syncthreads();

        float acch[WROWS / 8];
#pragma unroll
        for (int k = 0; k < WROWS / 8; k++) {
            int r = rbase + warp * (WROWS / 8) + k;
            acch[k] = 0.f;
            if (r < V)
                acch[k] = warp_dot(
                    reinterpret_cast<const float4*>(out_w + (long)r * (2 * H)),
                    sbuf4, lane);
        }

        // wait for ctx
        if (t == 0) while (g_ctxflag == 0) __nanosleep(64);
        __syncthreads();
        sbuf4[t] = reinterpret_cast<const float4*>(g_ctx)[t]; // ctx -> shared
        __syncthreads();

#pragma unroll
        for (int k = 0; k < WROWS / 8; k++) {
            int r = rbase + warp * (WROWS / 8) + k;
            if (r < V) {
                float acc = warp_dot(
                    reinterpret_cast<const float4*>(out_w + (long)r * (2 * H) + H),
                    sbuf4, lane);
                if (!lane) dout[r] = acch[k] + acc + out_b[r];
            }
        }
        return;
    }

    // ================= chain block =================
    const int nwarp = NCHAIN * (NT / 32);
    const int gw = b * (NT / 32) + warp;

    // ===== A: gates
    {
        const float* x = emb + (long)word[0] * H;
        sbuf4[t]       = reinterpret_cast<const float4*>(x)[t];
        sbuf4[256 + t] = reinterpret_cast<const float4*>(last_hidden)[t];
        __syncthreads();
        for (int r = gw; r < 6 * H; r += nwarp) {
            const float* W;
            const float4* vec4;
            float bias;
            float* out;
            if (r < 3 * H) {
                W = w_ih + (long)r * H; vec4 = sbuf4;        bias = b_ih[r]; out = &g_gi[r];
            } else {
                int rr = r - 3 * H;
                W = w_hh + (long)rr * H; vec4 = sbuf4 + 256; bias = b_hh[rr]; out = &g_gh[rr];
            }
            float acc = warp_dot(reinterpret_cast<const float4*>(W), vec4, lane);
            if (!lane) *out = acc + bias;
        }
    }
    chain_sync();

    // ===== B: GRU (blocks 0..3)
    if (b < 4) {
        int i = b * NT + t;
        float hp = last_hidden[i];
        float r = 1.f / (1.f + expf(-(g_gi[i] + g_gh[i])));
        float z = 1.f / (1.f + expf(-(g_gi[H + i] + g_gh[H + i])));
        float n = tanhf(g_gi[2 * H + i] + r * g_gh[2 * H + i]);
        float h = (1.f - z) * n + z * hp;
        g_h[i] = h;
        dout[V + i] = h;                      // hidden output
    }
    chain_sync();
    if (b == 0 && t == 0) g_hflag = 1;        // release workers (fenced by chain_sync)

    // ===== C: v partials (blocks 0..127)
    if (b < 128) {
        int jc = b >> 2;
        int c = (b & 3) * NT + t;
        const float* base = attn_w + (long)(jc * 32) * H + c;
        float s = 0.f;
#pragma unroll 8
        for (int j = 0; j < 32; j++)
            s += base[(long)j * H] * g_h[jc * 32 + j];
        g_vpart[jc][c] = s;
    }
    chain_sync();

    // ===== D: reduce v (blocks 0..3)
    if (b < 4) {
        int c = b * NT + t;
        float s = 0.f;
#pragma unroll
        for (int j = 0; j < 32; j++) s += g_vpart[j][c];
        g_v[c] = s;
    }
    chain_sync();

    // ===== E: scores[s] = enc[s].v  (attn_b is softmax-invariant)
    {
        sbuf4[256 + t] = reinterpret_cast<const float4*>(g_v)[t];
        __syncthreads();
        for (int s = gw; s < S; s += nwarp) {
            float acc = warp_dot(reinterpret_cast<const float4*>(enc + (long)s * H),
                                 sbuf4 + 256, lane);
            if (!lane) g_scores[s] = acc;
        }
    }
    chain_sync();

    // ===== F: softmax (block 0)
    if (b == 0) {
        float x[16];
        float m = -INFINITY;
#pragma unroll
        for (int k = 0; k < 16; k++) {
            x[k] = g_scores[t + NT * k];
            m = fmaxf(m, x[k]);
        }
#pragma unroll
        for (int o = 16; o; o >>= 1) m = fmaxf(m, __shfl_xor_sync(0xffffffffu, m, o));
        if (!lane) sbuf[warp] = m;
        __syncthreads();
        if (warp == 0) {
            m = (lane < 8) ? sbuf[lane] : -INFINITY;
#pragma unroll
            for (int o = 4; o; o >>= 1) m = fmaxf(m, __shfl_xor_sync(0xffffffffu, m, o));
            if (!lane) sbuf[64] = m;
        }
        __syncthreads();
        m = sbuf[64];
        float e[16];
        float sum = 0.f;
#pragma unroll
        for (int k = 0; k < 16; k++) { e[k] = expf(x[k] - m); sum += e[k]; }
        sum = warp_sum(sum);
        __syncthreads();
        if (!lane) sbuf[warp] = sum;
        __syncthreads();
        if (warp == 0) {
            sum = (lane < 8) ? sbuf[lane] : 0.f;
#pragma unroll
            for (int o = 4; o; o >>= 1) sum += __shfl_xor_sync(0xffffffffu, sum, o);
            if (!lane) sbuf[64] = sum;
        }
        __syncthreads();
        float inv = 1.f / sbuf[64];
#pragma unroll
        for (int k = 0; k < 16; k++) {
            float wt = e[k] * inv;
            g_w[t + NT * k] = wt;
            dout[V + H + t + NT * k] = wt;   // attn_weights output
        }
        __syncthreads();
    }
    chain_sync();

    // ===== G: ctx partials (blocks 0..127)
    if (b < 128) {
        int sc = b >> 2;
        int c = (b & 3) * NT + t;
        const float* base = enc + (long)(sc * 128) * H + c;
        float acc = 0.f;
#pragma unroll 8
        for (int s = 0; s < 128; s++)
            acc += g_w[sc * 128 + s] * base[(long)s * H];
        g_ctxpart[sc][c] = acc;
    }
    chain_sync();

    // ===== H: reduce ctx (blocks 0..3)
    if (b < 4) {
        int c = b * NT + t;
        float s = 0.f;
#pragma unroll
        for (int j = 0; j < 32; j++) s += g_ctxpart[j][c];
        g_ctx[c] = s;
    }
    chain_sync();
    if (b == 0 && t == 0) g_ctxflag = 1;      // release workers for ctx-half
}

// ---------------- launch ----------------
extern "C" void kernel_launch(void* const* d_in, const int* in_sizes, int n_in,
                              void* d_out, int out_size) {
    const int* word = (const int*)d_in[0];
    const float* last_hidden = (const float*)d_in[1];
    const float* enc = (const float*)d_in[2];
    const float* emb = (const float*)d_in[3];
    const float* w_ih = (const float*)d_in[4];
    const float* w_hh = (const float*)d_in[5];
    const float* b_ih = (const float*)d_in[6];
    const float* b_hh = (const float*)d_in[7];
    const float* attn_w = (const float*)d_in[8];
    // d_in[9] = attn_b : constant pre-softmax shift -> softmax-invariant, dropped
    const float* out_w = (const float*)d_in[10];
    const float* out_b = (const float*)d_in[11];
    float* dout = (float*)d_out;

    k_reset<<<1, 1>>>();
    k_fused<<<NCHAIN + NWORK, NT>>>(word, last_hidden, enc, emb, w_ih, w_hh,
                                    b_ih, b_hh, attn_w, out_w, out_b, dout);
}

// round 8
// speedup vs baseline: 1.1207x; 1.1207x over previous
#include <cuda_runtime.h>
#include <math.h>

#define H 1024
#define V 50257
#define S 4096
#define NT 256
#define NCHAIN 132            // chain blocks (first in dispatch order -> resident)
#define WROWS 48              // rows per worker block (8 warps x 6 rows)
#define NWORK ((V + WROWS - 1) / WROWS)   // 1048 worker blocks

// ---------------- scratch (__device__ globals) ----------------
__device__ float g_gi[3 * H];
__device__ float g_gh[3 * H];
__device__ float g_h[H];
__device__ float g_vpart[32][H];
__device__ float g_v[H];
__device__ float g_scores[S];
__device__ float g_w[S];
__device__ float g_ctxpart[128][H];   // 128 s-chunks of 32 rows
__device__ float g_ctx[H];
__device__ float g_logh[V];
__device__ unsigned g_cnt = 0;
__device__ unsigned g_gen = 0;
__device__ volatile unsigned g_hflag = 0;

// ---------------- helpers ----------------
__device__ __forceinline__ float warp_sum(float v) {
#pragma unroll
    for (int o = 16; o; o >>= 1) v += __shfl_xor_sync(0xffffffffu, v, o);
    return v;
}

// partial grid barrier over the NCHAIN chain blocks only
__device__ __forceinline__ void chain_sync() {
    __syncthreads();
    if (threadIdx.x == 0) {
        __threadfence();
        unsigned gen = *(volatile unsigned*)&g_gen;
        if (atomicAdd(&g_cnt, 1u) == NCHAIN - 1) {
            g_cnt = 0;
            __threadfence();
            *(volatile unsigned*)&g_gen = gen + 1;
        } else {
            while (*(volatile unsigned*)&g_gen == gen) { }
        }
        __threadfence();
    }
    __syncthreads();
}

// warp dot: 1024 floats from p vs shared vec
__device__ __forceinline__ float warp_dot(const float4* __restrict__ p,
                                          const float4* vec, int lane) {
    float acc = 0.f;
#pragma unroll
    for (int it = 0; it < 8; it++) {
        float4 w = p[it * 32 + lane];
        float4 c = vec[it * 32 + lane];
        acc += w.x * c.x + w.y * c.y + w.z * c.z + w.w * c.w;
    }
    return warp_sum(acc);
}

// ---------------- reset flag each replay ----------------
__global__ void k_reset() { g_hflag = 0; }

// ---------------- launch 1: chain blocks + single-phase h-half workers ----------
__global__ void __launch_bounds__(NT, 5)
k_fused(const int* __restrict__ word,
        const float* __restrict__ last_hidden,
        const float* __restrict__ enc,
        const float* __restrict__ emb,
        const float* __restrict__ w_ih,
        const float* __restrict__ w_hh,
        const float* __restrict__ b_ih,
        const float* __restrict__ b_hh,
        const float* __restrict__ attn_w,
        const float* __restrict__ out_w,
        float* __restrict__ dout) {
    __shared__ float4 sbuf4[512];
    float* sbuf = (float*)sbuf4;

    const int t = threadIdx.x;
    const int b = blockIdx.x;
    const int warp = t >> 5, lane = t & 31;

    if (b >= NCHAIN) {
        // ========== h-half worker: wait for h, dot 48 rows, write g_logh, retire
        const int rbase = (b - NCHAIN) * WROWS;
        if (t == 0) {
            while (g_hflag == 0) __nanosleep(128);
        }
        __syncthreads();
        __threadfence();                                   // acquire
        sbuf4[t] = reinterpret_cast<const float4*>(g_h)[t];
        __syncthreads();
#pragma unroll
        for (int k = 0; k < WROWS / 8; k++) {
            int r = rbase + warp * (WROWS / 8) + k;
            if (r < V) {
                float acc = warp_dot(
                    reinterpret_cast<const float4*>(out_w + (long)r * (2 * H)),
                    sbuf4, lane);
                if (!lane) g_logh[r] = acc;
            }
        }
        return;
    }

    // ================= chain block =================
    const int nwarp = NCHAIN * (NT / 32);
    const int gw = b * (NT / 32) + warp;

    // ===== A: gates  gi = w_ih@x + b_ih ; gh = w_hh@h_prev + b_hh
    {
        const float* x = emb + (long)word[0] * H;
        sbuf4[t]       = reinterpret_cast<const float4*>(x)[t];
        sbuf4[256 + t] = reinterpret_cast<const float4*>(last_hidden)[t];
        __syncthreads();
        for (int r = gw; r < 6 * H; r += nwarp) {
            const float* W;
            const float4* vec4;
            float bias;
            float* out;
            if (r < 3 * H) {
                W = w_ih + (long)r * H; vec4 = sbuf4;        bias = b_ih[r]; out = &g_gi[r];
            } else {
                int rr = r - 3 * H;
                W = w_hh + (long)rr * H; vec4 = sbuf4 + 256; bias = b_hh[rr]; out = &g_gh[rr];
            }
            float acc = warp_dot(reinterpret_cast<const float4*>(W), vec4, lane);
            if (!lane) *out = acc + bias;
        }
    }
    chain_sync();

    // ===== B: GRU (blocks 0..3)
    if (b < 4) {
        int i = b * NT + t;
        float hp = last_hidden[i];
        float r = 1.f / (1.f + expf(-(g_gi[i] + g_gh[i])));
        float z = 1.f / (1.f + expf(-(g_gi[H + i] + g_gh[H + i])));
        float n = tanhf(g_gi[2 * H + i] + r * g_gh[2 * H + i]);
        float h = (1.f - z) * n + z * hp;
        g_h[i] = h;
        dout[V + i] = h;                      // hidden output
    }
    chain_sync();
    if (b == 0 && t == 0) g_hflag = 1;        // release h-half workers

    // ===== C: v partials  v[c] = sum_j attn_w[j][c]*h[j]  (blocks 0..127)
    if (b < 128) {
        int jc = b >> 2;
        int c = (b & 3) * NT + t;
        const float* base = attn_w + (long)(jc * 32) * H + c;
        float s = 0.f;
#pragma unroll 8
        for (int j = 0; j < 32; j++)
            s += base[(long)j * H] * g_h[jc * 32 + j];
        g_vpart[jc][c] = s;
    }
    chain_sync();

    // ===== D: reduce v (blocks 0..3)
    if (b < 4) {
        int c = b * NT + t;
        float s = 0.f;
#pragma unroll
        for (int j = 0; j < 32; j++) s += g_vpart[j][c];
        g_v[c] = s;
    }
    chain_sync();

    // ===== E: scores[s] = enc[s].v  (attn_b is softmax-invariant)
    {
        sbuf4[256 + t] = reinterpret_cast<const float4*>(g_v)[t];
        __syncthreads();
        for (int s = gw; s < S; s += nwarp) {
            float acc = warp_dot(reinterpret_cast<const float4*>(enc + (long)s * H),
                                 sbuf4 + 256, lane);
            if (!lane) g_scores[s] = acc;
        }
    }
    chain_sync();

    // ===== F: softmax over 4096 (block 0)
    if (b == 0) {
        float x[16];
        float m = -INFINITY;
#pragma unroll
        for (int k = 0; k < 16; k++) {
            x[k] = g_scores[t + NT * k];
            m = fmaxf(m, x[k]);
        }
#pragma unroll
        for (int o = 16; o; o >>= 1) m = fmaxf(m, __shfl_xor_sync(0xffffffffu, m, o));
        if (!lane) sbuf[warp] = m;
        __syncthreads();
        if (warp == 0) {
            m = (lane < 8) ? sbuf[lane] : -INFINITY;
#pragma unroll
            for (int o = 4; o; o >>= 1) m = fmaxf(m, __shfl_xor_sync(0xffffffffu, m, o));
            if (!lane) sbuf[64] = m;
        }
        __syncthreads();
        m = sbuf[64];
        float e[16];
        float sum = 0.f;
#pragma unroll
        for (int k = 0; k < 16; k++) { e[k] = expf(x[k] - m); sum += e[k]; }
        sum = warp_sum(sum);
        __syncthreads();
        if (!lane) sbuf[warp] = sum;
        __syncthreads();
        if (warp == 0) {
            sum = (lane < 8) ? sbuf[lane] : 0.f;
#pragma unroll
            for (int o = 4; o; o >>= 1) sum += __shfl_xor_sync(0xffffffffu, sum, o);
            if (!lane) sbuf[64] = sum;
        }
        __syncthreads();
        float inv = 1.f / sbuf[64];
#pragma unroll
        for (int k = 0; k < 16; k++) {
            float wt = e[k] * inv;
            g_w[t + NT * k] = wt;
            dout[V + H + t + NT * k] = wt;   // attn_weights output
        }
        __syncthreads();
    }
    chain_sync();

    // ===== G: ctx partials, float4: 128 s-chunks of 32 rows, all 1024 cols/block
    if (b < 128) {
        const int sc = b;                         // rows [sc*32, sc*32+32)
        const float4* base = reinterpret_cast<const float4*>(enc + (long)(sc * 32) * H) + t;
        float4 acc = make_float4(0.f, 0.f, 0.f, 0.f);
#pragma unroll 8
        for (int s = 0; s < 32; s++) {
            float w = g_w[sc * 32 + s];
            float4 e = base[s * (H / 4)];
            acc.x += w * e.x; acc.y += w * e.y; acc.z += w * e.z; acc.w += w * e.w;
        }
        reinterpret_cast<float4*>(g_ctxpart[sc])[t] = acc;
    }
    chain_sync();

    // ===== H: reduce ctx (blocks 0..3)
    if (b < 4) {
        int c = b * NT + t;
        float s = 0.f;
#pragma unroll 16
        for (int j = 0; j < 128; j++) s += g_ctxpart[j][c];
        g_ctx[c] = s;
    }
    // kernel end publishes g_ctx / g_logh to next launch
}

// ---------------- launch 2: ctx-half + combine (flat, measured ~6.5 TB/s) -----
__global__ void k_logits_ctx(const float* __restrict__ out_w,
                             const float* __restrict__ out_b,
                             float* __restrict__ dout) {
    __shared__ float4 cv[256];
    int t = threadIdx.x;
    cv[t] = reinterpret_cast<const float4*>(g_ctx)[t];
    __syncthreads();
    int warp = t >> 5, lane = t & 31;
    int r = blockIdx.x * 8 + warp;
    if (r >= V) return;
    const float4* wr = reinterpret_cast<const float4*>(out_w + (long)r * (2 * H) + H);
    float acc = 0.f;
#pragma unroll
    for (int it = 0; it < 8; it++) {
        float4 w = wr[it * 32 + lane];
        float4 c = cv[it * 32 + lane];
        acc += w.x * c.x + w.y * c.y + w.z * c.z + w.w * c.w;
    }
    acc = warp_sum(acc);
    if (!lane) dout[r] = g_logh[r] + acc + out_b[r];
}

// ---------------- launch ----------------
extern "C" void kernel_launch(void* const* d_in, const int* in_sizes, int n_in,
                              void* d_out, int out_size) {
    const int* word = (const int*)d_in[0];
    const float* last_hidden = (const float*)d_in[1];
    const float* enc = (const float*)d_in[2];
    const float* emb = (const float*)d_in[3];
    const float* w_ih = (const float*)d_in[4];
    const float* w_hh = (const float*)d_in[5];
    const float* b_ih = (const float*)d_in[6];
    const float* b_hh = (const float*)d_in[7];
    const float* attn_w = (const float*)d_in[8];
    // d_in[9] = attn_b : constant pre-softmax shift -> softmax-invariant, dropped
    const float* out_w = (const float*)d_in[10];
    const float* out_b = (const float*)d_in[11];
    float* dout = (float*)d_out;

    k_reset<<<1, 1>>>();
    k_fused<<<NCHAIN + NWORK, NT>>>(word, last_hidden, enc, emb, w_ih, w_hh,
                                    b_ih, b_hh, attn_w, out_w, dout);
    k_logits_ctx<<<(V + 7) / 8, 256>>>(out_w, out_b, dout);
}

// round 9
// speedup vs baseline: 1.2720x; 1.1350x over previous
#include <cuda_runtime.h>
#include <math.h>

#define H 1024
#define V 50257
#define S 4096
#define NT 256
#define NCHAIN 256      // co-resident (2/SM x >=148 SMs); all barriers count these

// ---------------- scratch (__device__ globals) ----------------
__device__ float g_gi[3 * H];
__device__ float g_gh[3 * H];
__device__ float g_h[H];
__device__ float g_vpart[16][H];     // 16 j-chunks of 64 rows
__device__ float g_scores[S];
__device__ float g_ctxpart[64][H];   // 64 s-chunks of 64 rows
__device__ float g_ctx[H];
__device__ unsigned g_cnt = 0;
__device__ unsigned g_gen = 0;

// ---------------- helpers ----------------
__device__ __forceinline__ float warp_sum(float v) {
#pragma unroll
    for (int o = 16; o; o >>= 1) v += __shfl_xor_sync(0xffffffffu, v, o);
    return v;
}

__device__ __forceinline__ void chain_sync() {
    __syncthreads();
    if (threadIdx.x == 0) {
        __threadfence();
        unsigned gen = *(volatile unsigned*)&g_gen;
        if (atomicAdd(&g_cnt, 1u) == NCHAIN - 1) {
            g_cnt = 0;
            __threadfence();
            *(volatile unsigned*)&g_gen = gen + 1;
        } else {
            while (*(volatile unsigned*)&g_gen == gen) { }
        }
        __threadfence();
    }
    __syncthreads();
}

__device__ __forceinline__ float warp_dot(const float4* __restrict__ p,
                                          const float4* vec, int lane) {
    float acc = 0.f;
#pragma unroll
    for (int it = 0; it < 8; it++) {
        float4 w = p[it * 32 + lane];
        float4 c = vec[it * 32 + lane];
        acc += w.x * c.x + w.y * c.y + w.z * c.z + w.w * c.w;
    }
    return warp_sum(acc);
}

// ---------------- kernel 1: chain, 4 grid barriers ----------------
__global__ void __launch_bounds__(NT, 2)
k_chain(const int* __restrict__ word,
        const float* __restrict__ last_hidden,
        const float* __restrict__ enc,
        const float* __restrict__ emb,
        const float* __restrict__ w_ih,
        const float* __restrict__ w_hh,
        const float* __restrict__ b_ih,
        const float* __restrict__ b_hh,
        const float* __restrict__ attn_w,
        float* __restrict__ dout) {
    __shared__ float4 sbuf4[512];     // [0..255]: x then h ; [256..511]: h_prev then v
    __shared__ float red[64];
    __shared__ float bc;
    __shared__ float w_sh[64];
    float* h_sh = (float*)sbuf4;                 // after GRU
    float4* v_sh4 = sbuf4 + 256;                 // after vred

    const int t = threadIdx.x;
    const int b = blockIdx.x;
    const int warp = t >> 5, lane = t & 31;
    const int nwarp = NCHAIN * (NT / 32);        // 2048
    const int gw = b * (NT / 32) + warp;

    // ===== Phase 1: gates  gi = w_ih@x + b_ih ; gh = w_hh@h_prev + b_hh (all)
    {
        const float* x = emb + (long)word[0] * H;
        sbuf4[t]       = reinterpret_cast<const float4*>(x)[t];
        sbuf4[256 + t] = reinterpret_cast<const float4*>(last_hidden)[t];
        __syncthreads();
#pragma unroll
        for (int k = 0; k < 3; k++) {            // 6144 rows / 2048 warps
            int r = gw + k * nwarp;
            const float* W;
            const float4* vec4;
            float bias;
            float* out;
            if (r < 3 * H) {
                W = w_ih + (long)r * H; vec4 = sbuf4;        bias = b_ih[r]; out = &g_gi[r];
            } else {
                int rr = r - 3 * H;
                W = w_hh + (long)rr * H; vec4 = sbuf4 + 256; bias = b_hh[rr]; out = &g_gh[rr];
            }
            float acc = warp_dot(reinterpret_cast<const float4*>(W), vec4, lane);
            if (!lane) *out = acc + bias;
        }
    }
    chain_sync();   // barrier 1

    // ===== Phase 2a: GRU locally in EVERY block (h -> shared); block 0 publishes
    {
#pragma unroll
        for (int k = 0; k < 4; k++) {
            int i = t + NT * k;
            float hp = ((const float*)(sbuf4 + 256))[i];   // h_prev still in shared
            float r = 1.f / (1.f + expf(-(g_gi[i] + g_gh[i])));
            float z = 1.f / (1.f + expf(-(g_gi[H + i] + g_gh[H + i])));
            float n = tanhf(g_gi[2 * H + i] + r * g_gh[2 * H + i]);
            float h = (1.f - z) * n + z * hp;
            h_sh[i] = h;                                    // overwrites x (done)
            if (b == 0) { g_h[i] = h; dout[V + i] = h; }    // hidden output + logits input
        }
        __syncthreads();
    }

    // ===== Phase 2b: v partials (blocks 0..63): 16 chunks x 4 col-groups, 64 rows
    if (b < 64) {
        int jc = b >> 2;
        int c = (b & 3) * NT + t;
        const float* base = attn_w + (long)(jc * 64) * H + c;
        float s = 0.f;
#pragma unroll 8
        for (int j = 0; j < 64; j++)
            s += base[(long)j * H] * h_sh[jc * 64 + j];
        g_vpart[jc][c] = s;
    }
    chain_sync();   // barrier 2

    // ===== Phase 3a: local vred (all blocks): v -> shared (64KB L2 read/block)
    {
        float4 acc = make_float4(0.f, 0.f, 0.f, 0.f);
#pragma unroll
        for (int j = 0; j < 16; j++) {
            float4 p = reinterpret_cast<const float4*>(g_vpart[j])[t];
            acc.x += p.x; acc.y += p.y; acc.z += p.z; acc.w += p.w;
        }
        v_sh4[t] = acc;                                     // overwrites h_prev (done)
        __syncthreads();
    }

    // ===== Phase 3b: scores[s] = enc[s].v (all blocks; attn_b softmax-invariant)
    {
#pragma unroll
        for (int k = 0; k < 2; k++) {                       // 4096 / 2048 warps
            int s = gw + k * nwarp;
            float acc = warp_dot(reinterpret_cast<const float4*>(enc + (long)s * H),
                                 v_sh4, lane);
            if (!lane) g_scores[s] = acc;
        }
    }
    chain_sync();   // barrier 3

    // ===== Phase 4a: local softmax normalization (all blocks)
    float e_loc[16];
    {
        float x[16];
        float m = -INFINITY;
#pragma unroll
        for (int k = 0; k < 16; k++) {
            x[k] = g_scores[t + NT * k];
            m = fmaxf(m, x[k]);
        }
#pragma unroll
        for (int o = 16; o; o >>= 1) m = fmaxf(m, __shfl_xor_sync(0xffffffffu, m, o));
        if (!lane) red[warp] = m;
        __syncthreads();
        if (warp == 0) {
            m = (lane < 8) ? red[lane] : -INFINITY;
#pragma unroll
            for (int o = 4; o; o >>= 1) m = fmaxf(m, __shfl_xor_sync(0xffffffffu, m, o));
            if (!lane) bc = m;
        }
        __syncthreads();
        m = bc;
        float sum = 0.f;
#pragma unroll
        for (int k = 0; k < 16; k++) { e_loc[k] = expf(x[k] - m); sum += e_loc[k]; }
        sum = warp_sum(sum);
        __syncthreads();
        if (!lane) red[warp] = sum;
        __syncthreads();
        if (warp == 0) {
            sum = (lane < 8) ? red[lane] : 0.f;
#pragma unroll
            for (int o = 4; o; o >>= 1) sum += __shfl_xor_sync(0xffffffffu, sum, o);
            if (!lane) bc = sum;
        }
        __syncthreads();
    }
    const float inv = 1.f / bc;

    // block 0 writes attn_weights output
    if (b == 0) {
#pragma unroll
        for (int k = 0; k < 16; k++)
            dout[V + H + t + NT * k] = e_loc[k] * inv;
    }

    // ===== Phase 4b: ctx partials (all 256 blocks): 64 chunks x 4 col-groups, 64 rows
    {
        const int sc = b >> 2;                    // rows [sc*64, sc*64+64)
        const int c = (b & 3) * NT + t;
        // weights for this chunk from local softmax: rows sc*64 .. sc*64+63
        if (t < 64) {
            int s = sc * 64 + t;                  // s = t + 256*k with k = s>>8? no:
            // recompute weight directly: e = exp(scores[s]-m) -> we have e_loc only
            // for indices t+256k. Instead recompute from g_scores with bc-normalization:
            w_sh[t] = expf(g_scores[s] - (logf(0.f) == logf(0.f) ? 0.f : 0.f)) ;
        }
        __syncthreads();
        // NOTE: the line above is replaced below — see w_sh fill using m/inv.
        (void)w_sh;
        // Proper fill: each thread's e_loc covers s = t + 256k; chunk rows are
        // sc*64 + j (j<64) = 256*(j in which k?) -> use direct recompute with bc,
        // but we lost m... so recompute weights via e_loc scatter through shared:
        // Simplest correct path: threads whose (t + 256k) falls in chunk store it.
#pragma unroll
        for (int k = 0; k < 16; k++) {
            int s = t + NT * k;
            int j = s - sc * 64;
            if (j >= 0 && j < 64) w_sh[j] = e_loc[k] * inv;
        }
        __syncthreads();

        const float* base = enc + (long)(sc * 64) * H + c;
        float acc = 0.f;
#pragma unroll 8
        for (int s = 0; s < 64; s++)
            acc += w_sh[s] * base[(long)s * H];
        g_ctxpart[sc][c] = acc;
    }
    chain_sync();   // barrier 4

    // ===== Phase 5: ctxred (blocks 0..3) -> g_ctx; kernel end publishes
    if (b < 4) {
        int c = b * NT + t;
        float s = 0.f;
#pragma unroll
        for (int j = 0; j < 64; j++) s += g_ctxpart[j][c];
        g_ctx[c] = s;
    }
}

// ---------------- kernel 2: logits (flat, measured 6.57 TB/s) ----------------
__global__ void k_logits(const float* __restrict__ out_w,
                         const float* __restrict__ out_b,
                         float* __restrict__ dout) {
    __shared__ float4 cat[512];  // [h | ctx]
    int t = threadIdx.x;
    cat[t] = reinterpret_cast<const float4*>(g_h)[t];
    cat[256 + t] = reinterpret_cast<const float4*>(g_ctx)[t];
    __syncthreads();

    int warp = t >> 5, lane = t & 31;
    int r = blockIdx.x * 8 + warp;
    if (r >= V) return;
    const float4* wr = reinterpret_cast<const float4*>(out_w + (long)r * (2 * H));
    float acc = 0.f;
#pragma unroll
    for (int it = 0; it < 16; it++) {
        float4 w = wr[it * 32 + lane];
        float4 c = cat[it * 32 + lane];
        acc += w.x * c.x + w.y * c.y + w.z * c.z + w.w * c.w;
    }
    acc = warp_sum(acc);
    if (!lane) dout[r] = acc + out_b[r];
}

// ---------------- launch ----------------
extern "C" void kernel_launch(void* const* d_in, const int* in_sizes, int n_in,
                              void* d_out, int out_size) {
    const int* word = (const int*)d_in[0];
    const float* last_hidden = (const float*)d_in[1];
    const float* enc = (const float*)d_in[2];
    const float* emb = (const float*)d_in[3];
    const float* w_ih = (const float*)d_in[4];
    const float* w_hh = (const float*)d_in[5];
    const float* b_ih = (const float*)d_in[6];
    const float* b_hh = (const float*)d_in[7];
    const float* attn_w = (const float*)d_in[8];
    // d_in[9] = attn_b : constant pre-softmax shift -> softmax-invariant, dropped
    const float* out_w = (const float*)d_in[10];
    const float* out_b = (const float*)d_in[11];
    float* dout = (float*)d_out;

    k_chain<<<NCHAIN, NT>>>(word, last_hidden, enc, emb, w_ih, w_hh, b_ih, b_hh,
                            attn_w, dout);
    k_logits<<<(V + 7) / 8, 256>>>(out_w, out_b, dout);
}